// round 2
// baseline (speedup 1.0000x reference)
#include <cuda_runtime.h>
#include <math.h>

#define BB 64
#define TT 2048
#define II 64
#define HH 128
#define OO 64
#define GG 384   // 3*H

// Scratch for x_proj [B, T, 3H] — __device__ global (no cudaMalloc allowed).
__device__ float g_xproj[(size_t)BB * TT * GG];

typedef unsigned long long ull;

// Packed fp32x2 FMA (Blackwell sm_100a): d = a*b + c elementwise on 2 floats.
__device__ __forceinline__ ull ffma2(ull a, ull b, ull c) {
    ull d;
    asm("fma.rn.f32x2 %0, %1, %2, %3;" : "=l"(d) : "l"(a), "l"(b), "l"(c));
    return d;
}
__device__ __forceinline__ float red2(ull a) {
    float x, y;
    asm("mov.b64 {%0,%1}, %2;" : "=f"(x), "=f"(y) : "l"(a));
    return x + y;
}

__device__ __forceinline__ float sigmf(float x) {
    return 1.0f / (1.0f + __expf(-x));
}
// Numerically safe tanh via exp of negative magnitude (no overflow/NaN).
__device__ __forceinline__ float tanh_f(float x) {
    float e = __expf(-2.0f * fabsf(x));
    float r = (1.0f - e) / (1.0f + e);
    return copysignf(r, x);
}

// ---------------------------------------------------------------------------
// Kernel A: x_proj[b,t,g] = dot(x[b,t,:], W_ih[g,:]) + b_ih[g]
// Block = 64 rows (b*T+t positions) x all 384 output cols; 384 threads,
// one col per thread. W_ih row lives in registers (packed f32x2 pairs);
// x tile in SMEM, read as broadcast LDS.128.
// ---------------------------------------------------------------------------
__global__ void __launch_bounds__(384, 1) xproj_kernel(
    const float* __restrict__ x, const float* __restrict__ W_ih,
    const float* __restrict__ b_ih)
{
    __shared__ __align__(16) float xs[64 * II];  // 16 KB, contiguous tile
    int tid = threadIdx.x;
    size_t row0 = (size_t)blockIdx.x * 64;

    // Tile is contiguous in global memory: linear coalesced copy.
    for (int idx = tid; idx < 64 * II; idx += 384)
        xs[idx] = x[row0 * II + idx];

    // W_ih row for this thread's output column, packed into f32x2 pairs.
    ull w2[II / 2];
    {
        const ulonglong2* wp = (const ulonglong2*)(W_ih + (size_t)tid * II);
#pragma unroll
        for (int i = 0; i < II / 4; i++) {
            ulonglong2 v = wp[i];
            w2[2 * i] = v.x; w2[2 * i + 1] = v.y;
        }
    }
    float bias = b_ih[tid];
    __syncthreads();

    float* dst = g_xproj + row0 * GG + tid;
#pragma unroll 1
    for (int r = 0; r < 64; r++) {
        const ulonglong2* xp = (const ulonglong2*)(xs + r * II);
        ull a0 = 0ULL, a1 = 0ULL;
#pragma unroll
        for (int i = 0; i < II / 4; i++) {
            ulonglong2 v = xp[i];  // broadcast across lanes
            a0 = ffma2(w2[2 * i], v.x, a0);
            a1 = ffma2(w2[2 * i + 1], v.y, a1);
        }
        dst[(size_t)r * GG] = red2(a0) + red2(a1) + bias;
    }
}

// ---------------------------------------------------------------------------
// Kernel B: GRU recurrence. One CTA per batch element, persistent over T.
// 384 threads: thread t owns row t of W_hh (128 weights in registers).
// h in SMEM (broadcast reads). f32x2-packed dot: 64 FFMA2 + 32 LDS.128/step.
// Epilogue (threads 0..127) applies gates, updates h, streams latents.
// x_proj streamed with distance-1 register prefetch into a double buffer.
// ---------------------------------------------------------------------------
__global__ void __launch_bounds__(384, 1) gru_kernel(
    const float* __restrict__ W_hh, const float* __restrict__ b_hh,
    float* __restrict__ latents)
{
    __shared__ __align__(16) float h_s[HH];
    __shared__ float hg_s[GG];
    __shared__ float xg_s[2][GG];

    int tid = threadIdx.x;
    int b = blockIdx.x;

    // W_hh row in registers, packed as 64 f32x2 pairs (128 regs).
    ull w2[HH / 2];
    {
        const ulonglong2* wp = (const ulonglong2*)(W_hh + (size_t)tid * HH);
#pragma unroll
        for (int i = 0; i < HH / 4; i++) {
            ulonglong2 v = wp[i];
            w2[2 * i] = v.x; w2[2 * i + 1] = v.y;
        }
    }
    float bias = b_hh[tid];

    const float* xp = g_xproj + (size_t)b * TT * GG + tid;  // step with += GG
    float* lat = latents + (size_t)b * TT * HH + tid;       // step with += HH

    if (tid < HH) h_s[tid] = 0.0f;
    xg_s[0][tid] = xp[0];
    xp += GG;
    __syncthreads();

#pragma unroll 1
    for (int t = 0; t < TT; t++) {
        int cur = t & 1;
        // Prefetch next step's x-projection (hidden under the dot below).
        float xnext = 0.0f;
        if (t + 1 < TT) { xnext = xp[0]; xp += GG; }

        // hg[row] = dot(W_hh[row,:], h) + b_hh[row]
        ull a0 = 0ULL, a1 = 0ULL;
        const ulonglong2* hp = (const ulonglong2*)h_s;
#pragma unroll
        for (int i = 0; i < HH / 4; i++) {
            ulonglong2 v = hp[i];  // broadcast LDS.128
            a0 = ffma2(w2[2 * i], v.x, a0);
            a1 = ffma2(w2[2 * i + 1], v.y, a1);
        }
        hg_s[tid] = red2(a0) + red2(a1) + bias;
        __syncthreads();

        if (tid < HH) {
            float xr = xg_s[cur][tid];
            float xz = xg_s[cur][HH + tid];
            float xn = xg_s[cur][2 * HH + tid];
            float hr = hg_s[tid];
            float hz = hg_s[HH + tid];
            float hn = hg_s[2 * HH + tid];
            float rg = sigmf(xr + hr);
            float zg = sigmf(xz + hz);
            float ng = tanh_f(xn + rg * hn);
            float hnew = (1.0f - zg) * ng + zg * h_s[tid];
            h_s[tid] = hnew;
            lat[0] = hnew;
        }
        lat += HH;
        xg_s[cur ^ 1][tid] = xnext;  // fill next buffer (safe: after sync #1)
        __syncthreads();
    }
}

// ---------------------------------------------------------------------------
// Kernel C: output[b,t,o] = dot(latents[b,t,:], W_out[o,:]) + b_out[o]
// Block = 64 rows x 64 cols; 256 threads = (o, row-quarter). W_out row in
// registers, latents tile in SMEM (broadcast reads).
// ---------------------------------------------------------------------------
__global__ void __launch_bounds__(256, 1) out_kernel(
    const float* __restrict__ latents, const float* __restrict__ W_out,
    const float* __restrict__ b_out, float* __restrict__ out)
{
    __shared__ __align__(16) float lt[64 * HH];  // 32 KB
    int tid = threadIdx.x;
    size_t row0 = (size_t)blockIdx.x * 64;

    {
        const float4* src = (const float4*)(latents + row0 * HH);
        float4* dst = (float4*)lt;
        for (int idx = tid; idx < 64 * HH / 4; idx += 256) dst[idx] = src[idx];
    }

    int o = tid & 63;
    int q = tid >> 6;  // 0..3 -> 16 rows each

    ull w2[HH / 2];
    {
        const ulonglong2* wp = (const ulonglong2*)(W_out + (size_t)o * HH);
#pragma unroll
        for (int i = 0; i < HH / 4; i++) {
            ulonglong2 v = wp[i];
            w2[2 * i] = v.x; w2[2 * i + 1] = v.y;
        }
    }
    float bias = b_out[o];
    __syncthreads();

#pragma unroll 1
    for (int j = 0; j < 16; j++) {
        int r = q * 16 + j;
        const ulonglong2* lp = (const ulonglong2*)(lt + r * HH);
        ull a0 = 0ULL, a1 = 0ULL;
#pragma unroll
        for (int i = 0; i < HH / 4; i++) {
            ulonglong2 v = lp[i];  // broadcast across lanes
            a0 = ffma2(w2[2 * i], v.x, a0);
            a1 = ffma2(w2[2 * i + 1], v.y, a1);
        }
        out[(row0 + r) * OO + o] = red2(a0) + red2(a1) + bias;
    }
}

// ---------------------------------------------------------------------------
extern "C" void kernel_launch(void* const* d_in, const int* in_sizes, int n_in,
                              void* d_out, int out_size) {
    const float* x     = (const float*)d_in[0];
    const float* W_ih  = (const float*)d_in[1];
    const float* W_hh  = (const float*)d_in[2];
    const float* b_ih  = (const float*)d_in[3];
    const float* b_hh  = (const float*)d_in[4];
    const float* W_out = (const float*)d_in[5];
    const float* b_out = (const float*)d_in[6];

    float* out = (float*)d_out;                        // [B,T,O] first
    float* latents = out + (size_t)BB * TT * OO;       // then [B,T,H]

    xproj_kernel<<<(BB * TT) / 64, 384>>>(x, W_ih, b_ih);
    gru_kernel<<<BB, 384>>>(W_hh, b_hh, latents);
    out_kernel<<<(BB * TT) / 64, 256>>>(latents, W_out, b_out, out);
}